// round 11
// baseline (speedup 1.0000x reference)
#include <cuda_runtime.h>
#include <cuda_fp16.h>
#include <math.h>
#include <stdint.h>

#define HDIM 2048
#define IDIM 5632
#define NTOK 4096
#define NEXP 8
#define NASSIGN (NTOK * 2)
#define WCNT ((size_t)NEXP * IDIM * HDIM)   // elems per weight tensor
#define NPERSIST 304                        // 152 SMs x 2 CTAs

// -------- device scratch (sanctioned: __device__ globals) -------------------
__device__ __half g_xh[(size_t)NTOK * HDIM];      // x (fp16)
__device__ __half g_hh[(size_t)NASSIGN * IDIM];   // h = silu(g)*u (fp16)
__device__ __half g_gw16[WCNT];
__device__ __half g_uw16[WCNT];
__device__ __half g_dw16[WCNT];
__device__ int    g_cnt[NEXP];
__device__ int    g_tok[NEXP * NTOK];
__device__ float  g_wt [NEXP * NTOK];
__device__ int    g_perm[NASSIGN];
__device__ float  g_pwt [NASSIGN];
__device__ int    g_seg [NEXP + 1];

// ---------------------------------------------------------------- helpers ---
__device__ __forceinline__ uint32_t smem_u32(const void* p) {
    uint32_t a;
    asm("{ .reg .u64 t; cvta.to.shared.u64 t, %1; cvt.u32.u64 %0, t; }"
        : "=r"(a) : "l"(p));
    return a;
}
#define CPA16(dst, src) \
    asm volatile("cp.async.cg.shared.global [%0], [%1], 16;" :: "r"(dst), "l"(src))
#define CPA_COMMIT() asm volatile("cp.async.commit_group;" ::: "memory")
#define CPA_WAIT1()  asm volatile("cp.async.wait_group 1;" ::: "memory")
#define CPA_WAIT0()  asm volatile("cp.async.wait_group 0;" ::: "memory")

__device__ __forceinline__ void ldsm4(uint32_t* r, uint32_t a) {
    asm volatile("ldmatrix.sync.aligned.m8n8.x4.shared.b16 {%0,%1,%2,%3}, [%4];"
        : "=r"(r[0]), "=r"(r[1]), "=r"(r[2]), "=r"(r[3]) : "r"(a));
}
__device__ __forceinline__ void mma16816(float* d, const uint32_t* a, const uint32_t* b) {
    asm volatile(
        "mma.sync.aligned.m16n8k16.row.col.f32.f16.f16.f32 "
        "{%0,%1,%2,%3},{%4,%5,%6,%7},{%8,%9},{%0,%1,%2,%3};"
        : "+f"(d[0]), "+f"(d[1]), "+f"(d[2]), "+f"(d[3])
        : "r"(a[0]), "r"(a[1]), "r"(a[2]), "r"(a[3]), "r"(b[0]), "r"(b[1]));
}

// ---------------------------------------------------------------- prep -----
__global__ void prep_x_kernel(const float* __restrict__ x, float* __restrict__ out) {
    int i = blockIdx.x * 256 + threadIdx.x;
    if (i < NTOK * HDIM / 4) {
        float4 v = ((const float4*)x)[i];
        ((float4*)out)[i] = make_float4(0.f, 0.f, 0.f, 0.f);
        __half2 h0 = __floats2half2_rn(v.x, v.y);
        __half2 h1 = __floats2half2_rn(v.z, v.w);
        uint2 h;
        h.x = *reinterpret_cast<uint32_t*>(&h0);
        h.y = *reinterpret_cast<uint32_t*>(&h1);
        ((uint2*)g_xh)[i] = h;
    }
    if (i < NEXP) g_cnt[i] = 0;
}

__global__ void prep_w_kernel(const float* __restrict__ gw,
                              const float* __restrict__ uw,
                              const float* __restrict__ dw) {
    const size_t C8 = WCNT / 8;
    size_t i = (size_t)blockIdx.x * 256 + threadIdx.x;
    const float* src; __half* dst; size_t j;
    if (i < C8)            { src = gw; dst = g_gw16; j = i; }
    else if (i < 2 * C8)   { src = uw; dst = g_uw16; j = i - C8; }
    else if (i < 3 * C8)   { src = dw; dst = g_dw16; j = i - 2 * C8; }
    else return;
    float4 a = ((const float4*)src)[j * 2];
    float4 b = ((const float4*)src)[j * 2 + 1];
    __half2 p0 = __floats2half2_rn(a.x, a.y);
    __half2 p1 = __floats2half2_rn(a.z, a.w);
    __half2 p2 = __floats2half2_rn(b.x, b.y);
    __half2 p3 = __floats2half2_rn(b.z, b.w);
    uint4 o;
    o.x = *reinterpret_cast<uint32_t*>(&p0);
    o.y = *reinterpret_cast<uint32_t*>(&p1);
    o.z = *reinterpret_cast<uint32_t*>(&p2);
    o.w = *reinterpret_cast<uint32_t*>(&p3);
    ((uint4*)dst)[j] = o;
}

// -------------------------------------------------------------- router -----
__global__ __launch_bounds__(256) void router_kernel(
    const float* __restrict__ x, const float* __restrict__ rw) {
    int t0 = blockIdx.x * 4;
    int w = threadIdx.x >> 5, lane = threadIdx.x & 31;
    const float* wr = rw + w * HDIM;
    float s0 = 0.f, s1 = 0.f, s2 = 0.f, s3 = 0.f;
    const float* xr = x + (size_t)t0 * HDIM;
    for (int j = lane; j < HDIM; j += 32) {
        float wj = wr[j];
        s0 += xr[j] * wj;
        s1 += xr[HDIM + j] * wj;
        s2 += xr[2 * HDIM + j] * wj;
        s3 += xr[3 * HDIM + j] * wj;
    }
    #pragma unroll
    for (int o = 16; o; o >>= 1) {
        s0 += __shfl_xor_sync(0xffffffffu, s0, o);
        s1 += __shfl_xor_sync(0xffffffffu, s1, o);
        s2 += __shfl_xor_sync(0xffffffffu, s2, o);
        s3 += __shfl_xor_sync(0xffffffffu, s3, o);
    }
    __shared__ float logits[4][NEXP];
    if (lane == 0) {
        logits[0][w] = s0; logits[1][w] = s1; logits[2][w] = s2; logits[3][w] = s3;
    }
    __syncthreads();
    if (threadIdx.x < 4) {
        int t = t0 + threadIdx.x;
        float* lg = logits[threadIdx.x];
        float mx = lg[0];
        #pragma unroll
        for (int e = 1; e < NEXP; e++) mx = fmaxf(mx, lg[e]);
        float p[NEXP]; float den = 0.f;
        #pragma unroll
        for (int e = 0; e < NEXP; e++) { p[e] = expf(lg[e] - mx); den += p[e]; }
        float inv = 1.f / den;
        #pragma unroll
        for (int e = 0; e < NEXP; e++) p[e] *= inv;
        int i1 = 0;
        #pragma unroll
        for (int e = 1; e < NEXP; e++) if (p[e] > p[i1]) i1 = e;
        int i2 = (i1 == 0) ? 1 : 0;
        #pragma unroll
        for (int e = 0; e < NEXP; e++) if (e != i1 && p[e] > p[i2]) i2 = e;
        int pos1 = atomicAdd(&g_cnt[i1], 1);
        g_tok[i1 * NTOK + pos1] = t; g_wt[i1 * NTOK + pos1] = p[i1];
        int pos2 = atomicAdd(&g_cnt[i2], 1);
        g_tok[i2 * NTOK + pos2] = t; g_wt[i2 * NTOK + pos2] = p[i2];
    }
}

// ------------------------------------------------------------- compact -----
__global__ void compact_kernel() {
    const int e = blockIdx.x;
    __shared__ int base_s;
    if (threadIdx.x == 0) {
        int o = 0;
        #pragma unroll
        for (int k = 0; k < NEXP; k++) { if (k == e) base_s = o; o += g_cnt[k]; }
        if (e == 0) {
            int o2 = 0;
            #pragma unroll
            for (int k = 0; k < NEXP; k++) { g_seg[k] = o2; o2 += g_cnt[k]; }
            g_seg[NEXP] = o2;
        }
    }
    __syncthreads();
    int n = g_cnt[e], base = base_s;
    for (int p = threadIdx.x; p < n; p += blockDim.x) {
        g_perm[base + p] = g_tok[e * NTOK + p];
        g_pwt [base + p] = g_wt [e * NTOK + p];
    }
}

// --------------------------------------------- gate+up fused HMMA GEMM -----
// persistent CTAs, BM=128, BN=64 each (g,u), BK=64, 3-stage, 2 CTAs/SM
#define GU_STG   32768
#define GU_SMEM  (3 * GU_STG + 512)
#define GU_NT    (IDIM / 64)      // 88
#define GU_MT    (NTOK / 128)     // 32
__global__ __launch_bounds__(256, 2) void gateup_kernel() {
    extern __shared__ char smem[];
    const int tid = threadIdx.x;
    const uint32_t sb = smem_u32(smem);
    enum { AH = 0, BG = 16384, BU = 24576 };
    const uint32_t stgb[3] = { sb, sb + GU_STG, sb + 2 * GU_STG };
    int* toks = (int*)(smem + 3 * GU_STG);

    // consumer lane geometry (tile-invariant)
    const int l = tid & 31, wid = tid >> 5;
    const int wm = (wid & 3) * 32, wn = (wid >> 2) * 32;
    const int mat  = l >> 3;
    const int arow = (l & 7) + ((mat & 1) << 3);
    const int acm  = mat >> 1;
    const int brow = (l & 7) + ((mat >> 1) << 3);
    const int bcm  = mat & 1;
    const uint32_t xm = (uint32_t)(l & 7) << 4;
    const uint32_t aob[2] = { (uint32_t)(wm + arow) * 128, (uint32_t)(wm + 16 + arow) * 128 };
    const uint32_t bob[2] = { (uint32_t)(wn + brow) * 128, (uint32_t)(wn + 16 + brow) * 128 };
    const int r_ = l >> 2, c2 = (l & 3) * 2;

    for (int t = blockIdx.x; t < NEXP * GU_MT * GU_NT; t += NPERSIST) {
        const int e  = t / (GU_MT * GU_NT);
        const int rm = t % (GU_MT * GU_NT);
        const int m  = rm / GU_NT;
        const int n0 = (rm % GU_NT) * 64;
        const int s0 = g_seg[e], s1 = g_seg[e + 1];
        const int row0 = s0 + m * 128;
        if (row0 >= s1) continue;

        __syncthreads();   // protect toks from prior tile's readers
        for (int mm = tid; mm < 128; mm += 256) {
            int r = row0 + mm;
            toks[mm] = g_perm[(r < s1) ? r : (s1 - 1)];
        }
        __syncthreads();

        // producer addressing
        uint32_t a_dst[4]; size_t a_off[4];
        #pragma unroll
        for (int j = 0; j < 4; ++j) {
            int q = tid + 256 * j, ar = q >> 3, ac = q & 7;
            a_off[j] = (size_t)toks[ar] * HDIM + ac * 8;
            a_dst[j] = ar * 128 + (((uint32_t)ac << 4) ^ ((uint32_t)(ar & 7) << 4));
        }
        uint32_t b_dst[2]; size_t b_off[2];
        #pragma unroll
        for (int j = 0; j < 2; ++j) {
            int q = tid + 256 * j, br = q >> 3, bc = q & 7;
            b_off[j] = ((size_t)e * IDIM + n0 + br) * HDIM + bc * 8;
            b_dst[j] = br * 128 + (((uint32_t)bc << 4) ^ ((uint32_t)(br & 7) << 4));
        }

        float accg[2][4][4] = {}, accu[2][4][4] = {};
        const int NIT = HDIM / 64;

        #pragma unroll
        for (int s = 0; s < 2; ++s) {
            const uint32_t stg = stgb[s];
            const int k = s * 64;
            #pragma unroll
            for (int j = 0; j < 4; ++j) CPA16(stg + AH + a_dst[j], g_xh + a_off[j] + k);
            #pragma unroll
            for (int j = 0; j < 2; ++j) {
                CPA16(stg + BG + b_dst[j], g_gw16 + b_off[j] + k);
                CPA16(stg + BU + b_dst[j], g_uw16 + b_off[j] + k);
            }
            CPA_COMMIT();
        }

        int cons = 0, prod = 2;
        for (int it = 0; it < NIT; ++it) {
            CPA_WAIT1();
            __syncthreads();
            const uint32_t stg = stgb[cons];
            if (++cons == 3) cons = 0;
            if (it + 2 < NIT) {
                const uint32_t nst = stgb[prod];
                if (++prod == 3) prod = 0;
                const int k = (it + 2) * 64;
                #pragma unroll
                for (int j = 0; j < 4; ++j) CPA16(nst + AH + a_dst[j], g_xh + a_off[j] + k);
                #pragma unroll
                for (int j = 0; j < 2; ++j) {
                    CPA16(nst + BG + b_dst[j], g_gw16 + b_off[j] + k);
                    CPA16(nst + BU + b_dst[j], g_uw16 + b_off[j] + k);
                }
            }
            CPA_COMMIT();
            #pragma unroll
            for (int kk = 0; kk < 4; ++kk) {
                const uint32_t akb = (((uint32_t)(kk * 2 + acm)) << 4) ^ xm;
                const uint32_t bkb = (((uint32_t)(kk * 2 + bcm)) << 4) ^ xm;
                uint32_t ah[2][4], bg[2][4], bu[2][4];
                ldsm4(ah[0], stg + AH + aob[0] + akb);
                ldsm4(ah[1], stg + AH + aob[1] + akb);
                ldsm4(bg[0], stg + BG + bob[0] + bkb);
                ldsm4(bg[1], stg + BG + bob[1] + bkb);
                ldsm4(bu[0], stg + BU + bob[0] + bkb);
                ldsm4(bu[1], stg + BU + bob[1] + bkb);
                #pragma unroll
                for (int mi = 0; mi < 2; ++mi)
                    #pragma unroll
                    for (int ni = 0; ni < 4; ++ni) {
                        const int p = ni >> 1, hh = (ni & 1) * 2;
                        mma16816(accg[mi][ni], ah[mi], &bg[p][hh]);
                        mma16816(accu[mi][ni], ah[mi], &bu[p][hh]);
                    }
            }
        }
        CPA_WAIT0();
        __syncthreads();   // smem stages free for next tile

        // epilogue: h = silu(g)*u -> fp16
        #pragma unroll
        for (int mi = 0; mi < 2; ++mi)
            #pragma unroll
            for (int dd = 0; dd < 2; ++dd) {
                int grow = row0 + wm + mi * 16 + r_ + dd * 8;
                if (grow < s1) {
                    #pragma unroll
                    for (int ni = 0; ni < 4; ++ni) {
                        float g0 = accg[mi][ni][dd * 2],     g1 = accg[mi][ni][dd * 2 + 1];
                        float u0 = accu[mi][ni][dd * 2],     u1 = accu[mi][ni][dd * 2 + 1];
                        float h0 = g0 / (1.f + __expf(-g0)) * u0;
                        float h1 = g1 / (1.f + __expf(-g1)) * u1;
                        __half2 hp = __floats2half2_rn(h0, h1);
                        size_t off = (size_t)grow * IDIM + n0 + wn + ni * 8 + c2;
                        *(__half2*)(g_hh + off) = hp;
                    }
                }
            }
    }
}

// ----------------------------------------------- down HMMA GEMM ------------
// persistent CTAs, BM=128, BN=128, BK=64, 3-stage, 2 CTAs/SM
#define DN_STG   32768
#define DN_SMEM  (3 * DN_STG + 1024)
#define DN_NT    (HDIM / 128)     // 16
#define DN_MT    (NTOK / 128)     // 32
__global__ __launch_bounds__(256, 2) void down_kernel(float* __restrict__ out) {
    extern __shared__ char smem[];
    const int tid = threadIdx.x;
    const uint32_t sb = smem_u32(smem);
    enum { AH = 0, BB = 16384 };
    const uint32_t stgb[3] = { sb, sb + DN_STG, sb + 2 * DN_STG };
    int*   toks  = (int*)(smem + 3 * DN_STG);
    float* pwt_s = (float*)(smem + 3 * DN_STG + 512);

    const int l = tid & 31, wid = tid >> 5;
    const int wm = (wid & 3) * 32, wn = (wid >> 2) * 64;
    const int mat  = l >> 3;
    const int arow = (l & 7) + ((mat & 1) << 3);
    const int acm  = mat >> 1;
    const int brow = (l & 7) + ((mat >> 1) << 3);
    const int bcm  = mat & 1;
    const uint32_t xm = (uint32_t)(l & 7) << 4;
    const uint32_t aob[2] = { (uint32_t)(wm + arow) * 128, (uint32_t)(wm + 16 + arow) * 128 };
    uint32_t bob[4];
    #pragma unroll
    for (int p = 0; p < 4; ++p) bob[p] = (uint32_t)(wn + p * 16 + brow) * 128;
    const int r_ = l >> 2, c2 = (l & 3) * 2;

    for (int t = blockIdx.x; t < NEXP * DN_MT * DN_NT; t += NPERSIST) {
        const int e  = t / (DN_MT * DN_NT);
        const int rm = t % (DN_MT * DN_NT);
        const int m  = rm / DN_NT;
        const int n0 = (rm % DN_NT) * 128;
        const int s0 = g_seg[e], s1 = g_seg[e + 1];
        const int row0 = s0 + m * 128;
        if (row0 >= s1) continue;

        __syncthreads();   // protect toks/pwt from prior tile's epilogue readers
        for (int mm = tid; mm < 128; mm += 256) {
            int r = row0 + mm;
            int rc = (r < s1) ? r : (s1 - 1);
            toks[mm]  = g_perm[rc];
            pwt_s[mm] = g_pwt[rc];
        }
        __syncthreads();

        uint32_t a_dst[4]; size_t a_off[4];
        #pragma unroll
        for (int j = 0; j < 4; ++j) {
            int q = tid + 256 * j, ar = q >> 3, ac = q & 7;
            int rc = row0 + ar; if (rc >= s1) rc = s1 - 1;
            a_off[j] = (size_t)rc * IDIM + ac * 8;
            a_dst[j] = ar * 128 + (((uint32_t)ac << 4) ^ ((uint32_t)(ar & 7) << 4));
        }
        uint32_t b_dst[4]; size_t b_off[4];
        #pragma unroll
        for (int j = 0; j < 4; ++j) {
            int q = tid + 256 * j, br = q >> 3, bc = q & 7;
            b_off[j] = ((size_t)e * HDIM + n0 + br) * IDIM + bc * 8;
            b_dst[j] = br * 128 + (((uint32_t)bc << 4) ^ ((uint32_t)(br & 7) << 4));
        }

        float acc[2][8][4] = {};
        const int NIT = IDIM / 64;

        #pragma unroll
        for (int s = 0; s < 2; ++s) {
            const uint32_t stg = stgb[s];
            const int k = s * 64;
            #pragma unroll
            for (int j = 0; j < 4; ++j) {
                CPA16(stg + AH + a_dst[j], g_hh + a_off[j] + k);
                CPA16(stg + BB + b_dst[j], g_dw16 + b_off[j] + k);
            }
            CPA_COMMIT();
        }

        int cons = 0, prod = 2;
        for (int it = 0; it < NIT; ++it) {
            CPA_WAIT1();
            __syncthreads();
            const uint32_t stg = stgb[cons];
            if (++cons == 3) cons = 0;
            if (it + 2 < NIT) {
                const uint32_t nst = stgb[prod];
                if (++prod == 3) prod = 0;
                const int k = (it + 2) * 64;
                #pragma unroll
                for (int j = 0; j < 4; ++j) {
                    CPA16(nst + AH + a_dst[j], g_hh + a_off[j] + k);
                    CPA16(nst + BB + b_dst[j], g_dw16 + b_off[j] + k);
                }
            }
            CPA_COMMIT();
            #pragma unroll
            for (int kk = 0; kk < 4; ++kk) {
                const uint32_t akb = (((uint32_t)(kk * 2 + acm)) << 4) ^ xm;
                const uint32_t bkb = (((uint32_t)(kk * 2 + bcm)) << 4) ^ xm;
                uint32_t ah[2][4], bh[4][4];
                ldsm4(ah[0], stg + AH + aob[0] + akb);
                ldsm4(ah[1], stg + AH + aob[1] + akb);
                #pragma unroll
                for (int p = 0; p < 4; ++p) ldsm4(bh[p], stg + BB + bob[p] + bkb);
                #pragma unroll
                for (int mi = 0; mi < 2; ++mi)
                    #pragma unroll
                    for (int ni = 0; ni < 8; ++ni) {
                        const int p = ni >> 1, hh = (ni & 1) * 2;
                        mma16816(acc[mi][ni], ah[mi], &bh[p][hh]);
                    }
            }
        }
        CPA_WAIT0();
        __syncthreads();

        #pragma unroll
        for (int mi = 0; mi < 2; ++mi)
            #pragma unroll
            for (int dd = 0; dd < 2; ++dd) {
                int lrow = wm + mi * 16 + r_ + dd * 8;
                int grow = row0 + lrow;
                if (grow < s1) {
                    int   tok = toks[lrow];
                    float w   = pwt_s[lrow];
                    float* op = out + (size_t)tok * HDIM;
                    #pragma unroll
                    for (int ni = 0; ni < 8; ++ni) {
                        int col = n0 + wn + ni * 8 + c2;
                        atomicAdd(op + col,     w * acc[mi][ni][dd * 2]);
                        atomicAdd(op + col + 1, w * acc[mi][ni][dd * 2 + 1]);
                    }
                }
            }
    }
}

// ------------------------------------------------------------- launch ------
extern "C" void kernel_launch(void* const* d_in, const int* in_sizes, int n_in,
                              void* d_out, int out_size) {
    const float* x  = (const float*)d_in[0];
    const float* rw = (const float*)d_in[1];
    const float* gw = (const float*)d_in[2];
    const float* uw = (const float*)d_in[3];
    const float* dw = (const float*)d_in[4];
    float* out = (float*)d_out;

    cudaFuncSetAttribute(gateup_kernel, cudaFuncAttributeMaxDynamicSharedMemorySize,
                         GU_SMEM);
    cudaFuncSetAttribute(down_kernel, cudaFuncAttributeMaxDynamicSharedMemorySize,
                         DN_SMEM);

    prep_x_kernel<<<(NTOK * HDIM / 4 + 255) / 256, 256>>>(x, out);
    prep_w_kernel<<<(unsigned)((3 * (WCNT / 8) + 255) / 256), 256>>>(gw, uw, dw);
    router_kernel<<<NTOK / 4, 256>>>(x, rw);
    compact_kernel<<<NEXP, 256>>>();

    gateup_kernel<<<NPERSIST, 256, GU_SMEM>>>();
    down_kernel<<<NPERSIST, 256, DN_SMEM>>>(out);
}

// round 12
// speedup vs baseline: 1.0880x; 1.0880x over previous
#include <cuda_runtime.h>
#include <cuda_fp16.h>
#include <math.h>
#include <stdint.h>

#define HDIM 2048
#define IDIM 5632
#define NTOK 4096
#define NEXP 8
#define NASSIGN (NTOK * 2)
#define WCNT ((size_t)NEXP * IDIM * HDIM)   // elems per weight tensor

// -------- device scratch (sanctioned: __device__ globals) -------------------
__device__ __half g_xh[(size_t)NTOK * HDIM];      // x (fp16)
__device__ __half g_hh[(size_t)NASSIGN * IDIM];   // h = silu(g)*u (fp16)
__device__ __half g_gw16[WCNT];
__device__ __half g_uw16[WCNT];
__device__ __half g_dw16[WCNT];
__device__ int    g_cnt[NEXP];                    // zero-init at load; reset by gateup
__device__ int    g_tok[NEXP * NTOK];
__device__ float  g_wt [NEXP * NTOK];
__device__ int    g_perm[NASSIGN];
__device__ float  g_pwt [NASSIGN];
__device__ int    g_seg [NEXP + 1];

// ---------------------------------------------------------------- helpers ---
__device__ __forceinline__ uint32_t smem_u32(const void* p) {
    uint32_t a;
    asm("{ .reg .u64 t; cvta.to.shared.u64 t, %1; cvt.u32.u64 %0, t; }"
        : "=r"(a) : "l"(p));
    return a;
}
#define CPA16(dst, src) \
    asm volatile("cp.async.cg.shared.global [%0], [%1], 16;" :: "r"(dst), "l"(src))
#define CPA_COMMIT() asm volatile("cp.async.commit_group;" ::: "memory")
#define CPA_WAIT1()  asm volatile("cp.async.wait_group 1;" ::: "memory")

__device__ __forceinline__ void ldsm4(uint32_t* r, uint32_t a) {
    asm volatile("ldmatrix.sync.aligned.m8n8.x4.shared.b16 {%0,%1,%2,%3}, [%4];"
        : "=r"(r[0]), "=r"(r[1]), "=r"(r[2]), "=r"(r[3]) : "r"(a));
}
__device__ __forceinline__ void mma16816(float* d, const uint32_t* a, const uint32_t* b) {
    asm volatile(
        "mma.sync.aligned.m16n8k16.row.col.f32.f16.f16.f32 "
        "{%0,%1,%2,%3},{%4,%5,%6,%7},{%8,%9},{%0,%1,%2,%3};"
        : "+f"(d[0]), "+f"(d[1]), "+f"(d[2]), "+f"(d[3])
        : "r"(a[0]), "r"(a[1]), "r"(a[2]), "r"(a[3]), "r"(b[0]), "r"(b[1]));
}

// ------------------------------------------- fused prologue (3 sections) ----
// blocks [0, RT_B)            : router (8 expert logits, softmax, top-2)
// blocks [RT_B, RT_B+PX_B)    : zero out + convert x -> fp16
// blocks [RT_B+PX_B, total)   : convert 3 weight tensors -> fp16
#define RT_B  (NTOK / 4)                              // 1024
#define PX_B  ((NTOK * HDIM / 4 + 255) / 256)         // 8192
#define PW_B  ((unsigned)((3 * (WCNT / 8) + 255) / 256))
__global__ __launch_bounds__(256) void prologue_kernel(
    const float* __restrict__ x, const float* __restrict__ rw,
    const float* __restrict__ gw, const float* __restrict__ uw,
    const float* __restrict__ dw, float* __restrict__ out) {
    const unsigned bid = blockIdx.x;
    if (bid < RT_B) {
        // ---- router: 4 tokens per block ----
        int t0 = bid * 4;
        int w = threadIdx.x >> 5, lane = threadIdx.x & 31;
        const float* wr = rw + w * HDIM;
        float s0 = 0.f, s1 = 0.f, s2 = 0.f, s3 = 0.f;
        const float* xr = x + (size_t)t0 * HDIM;
        for (int j = lane; j < HDIM; j += 32) {
            float wj = wr[j];
            s0 += xr[j] * wj;
            s1 += xr[HDIM + j] * wj;
            s2 += xr[2 * HDIM + j] * wj;
            s3 += xr[3 * HDIM + j] * wj;
        }
        #pragma unroll
        for (int o = 16; o; o >>= 1) {
            s0 += __shfl_xor_sync(0xffffffffu, s0, o);
            s1 += __shfl_xor_sync(0xffffffffu, s1, o);
            s2 += __shfl_xor_sync(0xffffffffu, s2, o);
            s3 += __shfl_xor_sync(0xffffffffu, s3, o);
        }
        __shared__ float logits[4][NEXP];
        if (lane == 0) {
            logits[0][w] = s0; logits[1][w] = s1; logits[2][w] = s2; logits[3][w] = s3;
        }
        __syncthreads();
        if (threadIdx.x < 4) {
            int t = t0 + threadIdx.x;
            float* lg = logits[threadIdx.x];
            float mx = lg[0];
            #pragma unroll
            for (int e = 1; e < NEXP; e++) mx = fmaxf(mx, lg[e]);
            float p[NEXP]; float den = 0.f;
            #pragma unroll
            for (int e = 0; e < NEXP; e++) { p[e] = expf(lg[e] - mx); den += p[e]; }
            float inv = 1.f / den;
            #pragma unroll
            for (int e = 0; e < NEXP; e++) p[e] *= inv;
            int i1 = 0;
            #pragma unroll
            for (int e = 1; e < NEXP; e++) if (p[e] > p[i1]) i1 = e;
            int i2 = (i1 == 0) ? 1 : 0;
            #pragma unroll
            for (int e = 0; e < NEXP; e++) if (e != i1 && p[e] > p[i2]) i2 = e;
            int pos1 = atomicAdd(&g_cnt[i1], 1);
            g_tok[i1 * NTOK + pos1] = t; g_wt[i1 * NTOK + pos1] = p[i1];
            int pos2 = atomicAdd(&g_cnt[i2], 1);
            g_tok[i2 * NTOK + pos2] = t; g_wt[i2 * NTOK + pos2] = p[i2];
        }
    } else if (bid < RT_B + PX_B) {
        // ---- prep_x: zero out, x -> fp16 ----
        int i = (bid - RT_B) * 256 + threadIdx.x;
        if (i < NTOK * HDIM / 4) {
            float4 v = ((const float4*)x)[i];
            ((float4*)out)[i] = make_float4(0.f, 0.f, 0.f, 0.f);
            __half2 h0 = __floats2half2_rn(v.x, v.y);
            __half2 h1 = __floats2half2_rn(v.z, v.w);
            uint2 h;
            h.x = *reinterpret_cast<uint32_t*>(&h0);
            h.y = *reinterpret_cast<uint32_t*>(&h1);
            ((uint2*)g_xh)[i] = h;
        }
    } else {
        // ---- prep_w: weights -> fp16, 8 elems/thread ----
        const size_t C8 = WCNT / 8;
        size_t i = (size_t)(bid - RT_B - PX_B) * 256 + threadIdx.x;
        const float* src; __half* dst; size_t j;
        if (i < C8)            { src = gw; dst = g_gw16; j = i; }
        else if (i < 2 * C8)   { src = uw; dst = g_uw16; j = i - C8; }
        else if (i < 3 * C8)   { src = dw; dst = g_dw16; j = i - 2 * C8; }
        else return;
        float4 a = ((const float4*)src)[j * 2];
        float4 b = ((const float4*)src)[j * 2 + 1];
        __half2 p0 = __floats2half2_rn(a.x, a.y);
        __half2 p1 = __floats2half2_rn(a.z, a.w);
        __half2 p2 = __floats2half2_rn(b.x, b.y);
        __half2 p3 = __floats2half2_rn(b.z, b.w);
        uint4 o;
        o.x = *reinterpret_cast<uint32_t*>(&p0);
        o.y = *reinterpret_cast<uint32_t*>(&p1);
        o.z = *reinterpret_cast<uint32_t*>(&p2);
        o.w = *reinterpret_cast<uint32_t*>(&p3);
        ((uint4*)dst)[j] = o;
    }
}

// ------------------------------------------------------------- compact -----
// one block per expert; READS g_cnt only (reset happens later in gateup)
__global__ void compact_kernel() {
    const int e = blockIdx.x;
    __shared__ int base_s;
    if (threadIdx.x == 0) {
        int o = 0;
        #pragma unroll
        for (int k = 0; k < NEXP; k++) { if (k == e) base_s = o; o += g_cnt[k]; }
        if (e == 0) {
            int o2 = 0;
            #pragma unroll
            for (int k = 0; k < NEXP; k++) { g_seg[k] = o2; o2 += g_cnt[k]; }
            g_seg[NEXP] = o2;
        }
    }
    __syncthreads();
    int n = g_cnt[e], base = base_s;
    for (int p = threadIdx.x; p < n; p += blockDim.x) {
        g_perm[base + p] = g_tok[e * NTOK + p];
        g_pwt [base + p] = g_wt [e * NTOK + p];
    }
}

// --------------------------------------------- gate+up fused HMMA GEMM -----
// 256 thr, BM=128, BN=64 each (g,u), BK=64, 3-stage, 2 CTAs/SM
#define GU_STG   32768
#define GU_SMEM  (3 * GU_STG + 512)
__global__ __launch_bounds__(256, 2) void gateup_kernel() {
    extern __shared__ char smem[];
    const int tid = threadIdx.x;
    // reset g_cnt for next graph replay (compact has already consumed it)
    if (blockIdx.x == 0 && blockIdx.y == 0 && blockIdx.z == 0 && tid < NEXP)
        g_cnt[tid] = 0;
    const int e  = blockIdx.z;
    const int s0 = g_seg[e], s1 = g_seg[e + 1];
    const int row0 = s0 + blockIdx.y * 128;
    if (row0 >= s1) return;
    const int n0  = blockIdx.x * 64;
    const uint32_t sb = smem_u32(smem);
    enum { AH = 0, BG = 16384, BU = 24576 };
    const uint32_t stgb[3] = { sb, sb + GU_STG, sb + 2 * GU_STG };
    int* toks = (int*)(smem + 3 * GU_STG);

    for (int m = tid; m < 128; m += 256) {
        int r = row0 + m;
        toks[m] = g_perm[(r < s1) ? r : (s1 - 1)];
    }
    __syncthreads();

    uint32_t a_dst[4]; size_t a_off[4];
    #pragma unroll
    for (int j = 0; j < 4; ++j) {
        int q = tid + 256 * j, ar = q >> 3, ac = q & 7;
        a_off[j] = (size_t)toks[ar] * HDIM + ac * 8;
        a_dst[j] = ar * 128 + (((uint32_t)ac << 4) ^ ((uint32_t)(ar & 7) << 4));
    }
    uint32_t b_dst[2]; size_t b_off[2];
    #pragma unroll
    for (int j = 0; j < 2; ++j) {
        int q = tid + 256 * j, br = q >> 3, bc = q & 7;
        b_off[j] = ((size_t)e * IDIM + n0 + br) * HDIM + bc * 8;
        b_dst[j] = br * 128 + (((uint32_t)bc << 4) ^ ((uint32_t)(br & 7) << 4));
    }

    const int l = tid & 31, wid = tid >> 5;
    const int wm = (wid & 3) * 32, wn = (wid >> 2) * 32;
    const int mat  = l >> 3;
    const int arow = (l & 7) + ((mat & 1) << 3);
    const int acm  = mat >> 1;
    const int brow = (l & 7) + ((mat >> 1) << 3);
    const int bcm  = mat & 1;
    const uint32_t xm = (uint32_t)(l & 7) << 4;
    uint32_t aob[2] = { (uint32_t)(wm + arow) * 128, (uint32_t)(wm + 16 + arow) * 128 };
    uint32_t bob[2] = { (uint32_t)(wn + brow) * 128, (uint32_t)(wn + 16 + brow) * 128 };

    float accg[2][4][4] = {}, accu[2][4][4] = {};
    const int NIT = HDIM / 64;

    #pragma unroll
    for (int s = 0; s < 2; ++s) {
        const uint32_t stg = stgb[s];
        const int k = s * 64;
        #pragma unroll
        for (int j = 0; j < 4; ++j) CPA16(stg + AH + a_dst[j], g_xh + a_off[j] + k);
        #pragma unroll
        for (int j = 0; j < 2; ++j) {
            CPA16(stg + BG + b_dst[j], g_gw16 + b_off[j] + k);
            CPA16(stg + BU + b_dst[j], g_uw16 + b_off[j] + k);
        }
        CPA_COMMIT();
    }

    int cons = 0, prod = 2;
    for (int it = 0; it < NIT; ++it) {
        CPA_WAIT1();
        __syncthreads();
        const uint32_t stg = stgb[cons];
        if (++cons == 3) cons = 0;
        if (it + 2 < NIT) {
            const uint32_t nst = stgb[prod];
            if (++prod == 3) prod = 0;
            const int k = (it + 2) * 64;
            #pragma unroll
            for (int j = 0; j < 4; ++j) CPA16(nst + AH + a_dst[j], g_xh + a_off[j] + k);
            #pragma unroll
            for (int j = 0; j < 2; ++j) {
                CPA16(nst + BG + b_dst[j], g_gw16 + b_off[j] + k);
                CPA16(nst + BU + b_dst[j], g_uw16 + b_off[j] + k);
            }
        }
        CPA_COMMIT();
        #pragma unroll
        for (int kk = 0; kk < 4; ++kk) {
            const uint32_t akb = (((uint32_t)(kk * 2 + acm)) << 4) ^ xm;
            const uint32_t bkb = (((uint32_t)(kk * 2 + bcm)) << 4) ^ xm;
            uint32_t ah[2][4], bg[2][4], bu[2][4];
            ldsm4(ah[0], stg + AH + aob[0] + akb);
            ldsm4(ah[1], stg + AH + aob[1] + akb);
            ldsm4(bg[0], stg + BG + bob[0] + bkb);
            ldsm4(bg[1], stg + BG + bob[1] + bkb);
            ldsm4(bu[0], stg + BU + bob[0] + bkb);
            ldsm4(bu[1], stg + BU + bob[1] + bkb);
            #pragma unroll
            for (int mi = 0; mi < 2; ++mi)
                #pragma unroll
                for (int ni = 0; ni < 4; ++ni) {
                    const int p = ni >> 1, hh = (ni & 1) * 2;
                    mma16816(accg[mi][ni], ah[mi], &bg[p][hh]);
                    mma16816(accu[mi][ni], ah[mi], &bu[p][hh]);
                }
        }
    }

    // epilogue: h = silu(g)*u -> fp16
    const int r_ = l >> 2, c2 = (l & 3) * 2;
    #pragma unroll
    for (int mi = 0; mi < 2; ++mi)
        #pragma unroll
        for (int dd = 0; dd < 2; ++dd) {
            int grow = row0 + wm + mi * 16 + r_ + dd * 8;
            if (grow < s1) {
                #pragma unroll
                for (int ni = 0; ni < 4; ++ni) {
                    float g0 = accg[mi][ni][dd * 2],     g1 = accg[mi][ni][dd * 2 + 1];
                    float u0 = accu[mi][ni][dd * 2],     u1 = accu[mi][ni][dd * 2 + 1];
                    float h0 = g0 / (1.f + __expf(-g0)) * u0;
                    float h1 = g1 / (1.f + __expf(-g1)) * u1;
                    __half2 hp = __floats2half2_rn(h0, h1);
                    size_t off = (size_t)grow * IDIM + n0 + wn + ni * 8 + c2;
                    *(__half2*)(g_hh + off) = hp;
                }
            }
        }
}

// ----------------------------------------------- down HMMA GEMM ------------
// 256 thr, BM=128, BN=128, BK=64, 3-stage, 2 CTAs/SM
#define DN_STG   32768
#define DN_SMEM  (3 * DN_STG + 1024)
__global__ __launch_bounds__(256, 2) void down_kernel(float* __restrict__ out) {
    extern __shared__ char smem[];
    const int e  = blockIdx.z;
    const int s0 = g_seg[e], s1 = g_seg[e + 1];
    const int row0 = s0 + blockIdx.y * 128;
    if (row0 >= s1) return;
    const int n0  = blockIdx.x * 128;
    const int tid = threadIdx.x;
    const uint32_t sb = smem_u32(smem);
    enum { AH = 0, BB = 16384 };
    const uint32_t stgb[3] = { sb, sb + DN_STG, sb + 2 * DN_STG };
    int*   toks  = (int*)(smem + 3 * DN_STG);
    float* pwt_s = (float*)(smem + 3 * DN_STG + 512);

    for (int m = tid; m < 128; m += 256) {
        int r = row0 + m;
        int rc = (r < s1) ? r : (s1 - 1);
        toks[m]  = g_perm[rc];
        pwt_s[m] = g_pwt[rc];
    }
    __syncthreads();

    uint32_t a_dst[4]; size_t a_off[4];
    #pragma unroll
    for (int j = 0; j < 4; ++j) {
        int q = tid + 256 * j, ar = q >> 3, ac = q & 7;
        int rc = row0 + ar; if (rc >= s1) rc = s1 - 1;
        a_off[j] = (size_t)rc * IDIM + ac * 8;
        a_dst[j] = ar * 128 + (((uint32_t)ac << 4) ^ ((uint32_t)(ar & 7) << 4));
    }
    uint32_t b_dst[4]; size_t b_off[4];
    #pragma unroll
    for (int j = 0; j < 4; ++j) {
        int q = tid + 256 * j, br = q >> 3, bc = q & 7;
        b_off[j] = ((size_t)e * HDIM + n0 + br) * IDIM + bc * 8;
        b_dst[j] = br * 128 + (((uint32_t)bc << 4) ^ ((uint32_t)(br & 7) << 4));
    }

    const int l = tid & 31, wid = tid >> 5;
    const int wm = (wid & 3) * 32, wn = (wid >> 2) * 64;
    const int mat  = l >> 3;
    const int arow = (l & 7) + ((mat & 1) << 3);
    const int acm  = mat >> 1;
    const int brow = (l & 7) + ((mat >> 1) << 3);
    const int bcm  = mat & 1;
    const uint32_t xm = (uint32_t)(l & 7) << 4;
    uint32_t aob[2] = { (uint32_t)(wm + arow) * 128, (uint32_t)(wm + 16 + arow) * 128 };
    uint32_t bob[4];
    #pragma unroll
    for (int p = 0; p < 4; ++p) bob[p] = (uint32_t)(wn + p * 16 + brow) * 128;

    float acc[2][8][4] = {};
    const int NIT = IDIM / 64;

    #pragma unroll
    for (int s = 0; s < 2; ++s) {
        const uint32_t stg = stgb[s];
        const int k = s * 64;
        #pragma unroll
        for (int j = 0; j < 4; ++j) {
            CPA16(stg + AH + a_dst[j], g_hh + a_off[j] + k);
            CPA16(stg + BB + b_dst[j], g_dw16 + b_off[j] + k);
        }
        CPA_COMMIT();
    }

    int cons = 0, prod = 2;
    for (int it = 0; it < NIT; ++it) {
        CPA_WAIT1();
        __syncthreads();
        const uint32_t stg = stgb[cons];
        if (++cons == 3) cons = 0;
        if (it + 2 < NIT) {
            const uint32_t nst = stgb[prod];
            if (++prod == 3) prod = 0;
            const int k = (it + 2) * 64;
            #pragma unroll
            for (int j = 0; j < 4; ++j) {
                CPA16(nst + AH + a_dst[j], g_hh + a_off[j] + k);
                CPA16(nst + BB + b_dst[j], g_dw16 + b_off[j] + k);
            }
        }
        CPA_COMMIT();
        #pragma unroll
        for (int kk = 0; kk < 4; ++kk) {
            const uint32_t akb = (((uint32_t)(kk * 2 + acm)) << 4) ^ xm;
            const uint32_t bkb = (((uint32_t)(kk * 2 + bcm)) << 4) ^ xm;
            uint32_t ah[2][4], bh[4][4];
            ldsm4(ah[0], stg + AH + aob[0] + akb);
            ldsm4(ah[1], stg + AH + aob[1] + akb);
            #pragma unroll
            for (int p = 0; p < 4; ++p) ldsm4(bh[p], stg + BB + bob[p] + bkb);
            #pragma unroll
            for (int mi = 0; mi < 2; ++mi)
                #pragma unroll
                for (int ni = 0; ni < 8; ++ni) {
                    const int p = ni >> 1, hh = (ni & 1) * 2;
                    mma16816(acc[mi][ni], ah[mi], &bh[p][hh]);
                }
        }
    }

    const int r_ = l >> 2, c2 = (l & 3) * 2;
    #pragma unroll
    for (int mi = 0; mi < 2; ++mi)
        #pragma unroll
        for (int dd = 0; dd < 2; ++dd) {
            int lrow = wm + mi * 16 + r_ + dd * 8;
            int grow = row0 + lrow;
            if (grow < s1) {
                int   tok = toks[lrow];
                float w   = pwt_s[lrow];
                float* op = out + (size_t)tok * HDIM;
                #pragma unroll
                for (int ni = 0; ni < 8; ++ni) {
                    int col = n0 + wn + ni * 8 + c2;
                    atomicAdd(op + col,     w * acc[mi][ni][dd * 2]);
                    atomicAdd(op + col + 1, w * acc[mi][ni][dd * 2 + 1]);
                }
            }
        }
}

// ------------------------------------------------------------- launch ------
extern "C" void kernel_launch(void* const* d_in, const int* in_sizes, int n_in,
                              void* d_out, int out_size) {
    const float* x  = (const float*)d_in[0];
    const float* rw = (const float*)d_in[1];
    const float* gw = (const float*)d_in[2];
    const float* uw = (const float*)d_in[3];
    const float* dw = (const float*)d_in[4];
    float* out = (float*)d_out;

    cudaFuncSetAttribute(gateup_kernel, cudaFuncAttributeMaxDynamicSharedMemorySize,
                         GU_SMEM);
    cudaFuncSetAttribute(down_kernel, cudaFuncAttributeMaxDynamicSharedMemorySize,
                         DN_SMEM);

    prologue_kernel<<<RT_B + PX_B + PW_B, 256>>>(x, rw, gw, uw, dw, out);
    compact_kernel<<<NEXP, 256>>>();

    dim3 g1(IDIM / 64, NTOK / 128, NEXP);
    gateup_kernel<<<g1, 256, GU_SMEM>>>();

    dim3 g2(HDIM / 128, NTOK / 128, NEXP);
    down_kernel<<<g2, 256, DN_SMEM>>>(out);
}

// round 13
// speedup vs baseline: 1.1214x; 1.0307x over previous
#include <cuda_runtime.h>
#include <cuda_fp16.h>
#include <math.h>
#include <stdint.h>

#define HDIM 2048
#define IDIM 5632
#define NTOK 4096
#define NEXP 8
#define NASSIGN (NTOK * 2)
#define WCNT ((size_t)NEXP * IDIM * HDIM)   // elems per weight tensor

// -------- device scratch (sanctioned: __device__ globals) -------------------
__device__ __half g_xh[(size_t)NTOK * HDIM];      // x (fp16)
__device__ __half g_hh[(size_t)NASSIGN * IDIM];   // h = silu(g)*u (fp16)
__device__ __half g_gw16[WCNT];
__device__ __half g_uw16[WCNT];
__device__ __half g_dw16[WCNT];
__device__ int    g_cnt[NEXP];                    // zero-init at load; reset by gateup
__device__ int    g_tok[NEXP * NTOK];
__device__ float  g_wt [NEXP * NTOK];
__device__ int    g_perm[NASSIGN];
__device__ float  g_pwt [NASSIGN];
__device__ int    g_seg [NEXP + 1];

// ---------------------------------------------------------------- helpers ---
__device__ __forceinline__ uint32_t smem_u32(const void* p) {
    uint32_t a;
    asm("{ .reg .u64 t; cvta.to.shared.u64 t, %1; cvt.u32.u64 %0, t; }"
        : "=r"(a) : "l"(p));
    return a;
}
#define CPA16(dst, src) \
    asm volatile("cp.async.cg.shared.global [%0], [%1], 16;" :: "r"(dst), "l"(src))
#define CPA_COMMIT() asm volatile("cp.async.commit_group;" ::: "memory")
#define CPA_WAIT1()  asm volatile("cp.async.wait_group 1;" ::: "memory")

__device__ __forceinline__ void ldsm4(uint32_t* r, uint32_t a) {
    asm volatile("ldmatrix.sync.aligned.m8n8.x4.shared.b16 {%0,%1,%2,%3}, [%4];"
        : "=r"(r[0]), "=r"(r[1]), "=r"(r[2]), "=r"(r[3]) : "r"(a));
}
__device__ __forceinline__ void mma16816(float* d, const uint32_t* a, const uint32_t* b) {
    asm volatile(
        "mma.sync.aligned.m16n8k16.row.col.f32.f16.f16.f32 "
        "{%0,%1,%2,%3},{%4,%5,%6,%7},{%8,%9},{%0,%1,%2,%3};"
        : "+f"(d[0]), "+f"(d[1]), "+f"(d[2]), "+f"(d[3])
        : "r"(a[0]), "r"(a[1]), "r"(a[2]), "r"(a[3]), "r"(b[0]), "r"(b[1]));
}
__device__ __forceinline__ void cvt8(const float* __restrict__ src, __half* __restrict__ dst,
                                     size_t j) {
    float4 a = ((const float4*)src)[j * 2];
    float4 b = ((const float4*)src)[j * 2 + 1];
    __half2 p0 = __floats2half2_rn(a.x, a.y);
    __half2 p1 = __floats2half2_rn(a.z, a.w);
    __half2 p2 = __floats2half2_rn(b.x, b.y);
    __half2 p3 = __floats2half2_rn(b.z, b.w);
    uint4 o;
    o.x = *reinterpret_cast<uint32_t*>(&p0);
    o.y = *reinterpret_cast<uint32_t*>(&p1);
    o.z = *reinterpret_cast<uint32_t*>(&p2);
    o.w = *reinterpret_cast<uint32_t*>(&p3);
    ((uint4*)dst)[j] = o;
}

// ------------------------------------------- fused prologue (3 sections) ----
// blocks [0, RT_B)            : router
// blocks [RT_B, RT_B+PX_B)    : zero out + convert x -> fp16
// blocks [RT_B+PX_B, total)   : convert gate_w, up_w -> fp16 (down_w deferred)
#define RT_B  (NTOK / 4)                              // 1024
#define PX_B  ((NTOK * HDIM / 4 + 255) / 256)         // 8192
#define PW_B  ((unsigned)((2 * (WCNT / 8) + 255) / 256))
__global__ __launch_bounds__(256) void prologue_kernel(
    const float* __restrict__ x, const float* __restrict__ rw,
    const float* __restrict__ gw, const float* __restrict__ uw,
    float* __restrict__ out) {
    const unsigned bid = blockIdx.x;
    if (bid < RT_B) {
        int t0 = bid * 4;
        int w = threadIdx.x >> 5, lane = threadIdx.x & 31;
        const float* wr = rw + w * HDIM;
        float s0 = 0.f, s1 = 0.f, s2 = 0.f, s3 = 0.f;
        const float* xr = x + (size_t)t0 * HDIM;
        for (int j = lane; j < HDIM; j += 32) {
            float wj = wr[j];
            s0 += xr[j] * wj;
            s1 += xr[HDIM + j] * wj;
            s2 += xr[2 * HDIM + j] * wj;
            s3 += xr[3 * HDIM + j] * wj;
        }
        #pragma unroll
        for (int o = 16; o; o >>= 1) {
            s0 += __shfl_xor_sync(0xffffffffu, s0, o);
            s1 += __shfl_xor_sync(0xffffffffu, s1, o);
            s2 += __shfl_xor_sync(0xffffffffu, s2, o);
            s3 += __shfl_xor_sync(0xffffffffu, s3, o);
        }
        __shared__ float logits[4][NEXP];
        if (lane == 0) {
            logits[0][w] = s0; logits[1][w] = s1; logits[2][w] = s2; logits[3][w] = s3;
        }
        __syncthreads();
        if (threadIdx.x < 4) {
            int t = t0 + threadIdx.x;
            float* lg = logits[threadIdx.x];
            float mx = lg[0];
            #pragma unroll
            for (int e = 1; e < NEXP; e++) mx = fmaxf(mx, lg[e]);
            float p[NEXP]; float den = 0.f;
            #pragma unroll
            for (int e = 0; e < NEXP; e++) { p[e] = expf(lg[e] - mx); den += p[e]; }
            float inv = 1.f / den;
            #pragma unroll
            for (int e = 0; e < NEXP; e++) p[e] *= inv;
            int i1 = 0;
            #pragma unroll
            for (int e = 1; e < NEXP; e++) if (p[e] > p[i1]) i1 = e;
            int i2 = (i1 == 0) ? 1 : 0;
            #pragma unroll
            for (int e = 0; e < NEXP; e++) if (e != i1 && p[e] > p[i2]) i2 = e;
            int pos1 = atomicAdd(&g_cnt[i1], 1);
            g_tok[i1 * NTOK + pos1] = t; g_wt[i1 * NTOK + pos1] = p[i1];
            int pos2 = atomicAdd(&g_cnt[i2], 1);
            g_tok[i2 * NTOK + pos2] = t; g_wt[i2 * NTOK + pos2] = p[i2];
        }
    } else if (bid < RT_B + PX_B) {
        int i = (bid - RT_B) * 256 + threadIdx.x;
        if (i < NTOK * HDIM / 4) {
            float4 v = ((const float4*)x)[i];
            ((float4*)out)[i] = make_float4(0.f, 0.f, 0.f, 0.f);
            __half2 h0 = __floats2half2_rn(v.x, v.y);
            __half2 h1 = __floats2half2_rn(v.z, v.w);
            uint2 h;
            h.x = *reinterpret_cast<uint32_t*>(&h0);
            h.y = *reinterpret_cast<uint32_t*>(&h1);
            ((uint2*)g_xh)[i] = h;
        }
    } else {
        const size_t C8 = WCNT / 8;
        size_t i = (size_t)(bid - RT_B - PX_B) * 256 + threadIdx.x;
        if (i < C8)          cvt8(gw, g_gw16, i);
        else if (i < 2 * C8) cvt8(uw, g_uw16, i - C8);
    }
}

// ------------------------------------------------------------- compact -----
__global__ void compact_kernel() {
    const int e = blockIdx.x;
    __shared__ int base_s;
    if (threadIdx.x == 0) {
        int o = 0;
        #pragma unroll
        for (int k = 0; k < NEXP; k++) { if (k == e) base_s = o; o += g_cnt[k]; }
        if (e == 0) {
            int o2 = 0;
            #pragma unroll
            for (int k = 0; k < NEXP; k++) { g_seg[k] = o2; o2 += g_cnt[k]; }
            g_seg[NEXP] = o2;
        }
    }
    __syncthreads();
    int n = g_cnt[e], base = base_s;
    for (int p = threadIdx.x; p < n; p += blockDim.x) {
        g_perm[base + p] = g_tok[e * NTOK + p];
        g_pwt [base + p] = g_wt [e * NTOK + p];
    }
}

// --------------------------------------------- gate+up fused HMMA GEMM -----
// flattened 1D grid: 16 GEMM tiles then 1 dw-conversion block, repeating.
// GEMM: 256 thr, BM=128, BN=64 each (g,u), BK=64, 3-stage, 2 CTAs/SM
#define GU_STG    32768
#define GU_SMEM   (3 * GU_STG + 512)
#define GU_TILES  (NEXP * (NTOK / 128) * (IDIM / 64))   // 22528
#define DW_CONV   1408                                   // GU_TILES / 16
#define DW_VEC8   ((WCNT / 8) / DW_CONV)                 // 8192 vec8 per conv block
__global__ __launch_bounds__(256, 2) void gateup_kernel(const float* __restrict__ dw) {
    extern __shared__ char smem[];
    const int tid = threadIdx.x;
    const unsigned bx = blockIdx.x;
    if (bx == 0 && tid < NEXP) g_cnt[tid] = 0;   // reset for next graph replay

    const unsigned group = bx / 17, pos = bx % 17;
    if (pos == 16) {
        // ---- dw -> fp16 conversion slice (overlapped with GEMM tiles) ----
        size_t base8 = (size_t)group * DW_VEC8;
        #pragma unroll 4
        for (int j = 0; j < (int)(DW_VEC8 / 256); ++j)
            cvt8(dw, g_dw16, base8 + (size_t)j * 256 + tid);
        return;
    }
    const int t  = group * 16 + pos;
    const int e  = t / ((NTOK / 128) * (IDIM / 64));
    const int rm = t % ((NTOK / 128) * (IDIM / 64));
    const int m  = rm / (IDIM / 64);
    const int n0 = (rm % (IDIM / 64)) * 64;
    const int s0 = g_seg[e], s1 = g_seg[e + 1];
    const int row0 = s0 + m * 128;
    if (row0 >= s1) return;
    const uint32_t sb = smem_u32(smem);
    enum { AH = 0, BG = 16384, BU = 24576 };
    const uint32_t stgb[3] = { sb, sb + GU_STG, sb + 2 * GU_STG };
    int* toks = (int*)(smem + 3 * GU_STG);

    for (int mm = tid; mm < 128; mm += 256) {
        int r = row0 + mm;
        toks[mm] = g_perm[(r < s1) ? r : (s1 - 1)];
    }
    __syncthreads();

    uint32_t a_dst[4]; size_t a_off[4];
    #pragma unroll
    for (int j = 0; j < 4; ++j) {
        int q = tid + 256 * j, ar = q >> 3, ac = q & 7;
        a_off[j] = (size_t)toks[ar] * HDIM + ac * 8;
        a_dst[j] = ar * 128 + (((uint32_t)ac << 4) ^ ((uint32_t)(ar & 7) << 4));
    }
    uint32_t b_dst[2]; size_t b_off[2];
    #pragma unroll
    for (int j = 0; j < 2; ++j) {
        int q = tid + 256 * j, br = q >> 3, bc = q & 7;
        b_off[j] = ((size_t)e * IDIM + n0 + br) * HDIM + bc * 8;
        b_dst[j] = br * 128 + (((uint32_t)bc << 4) ^ ((uint32_t)(br & 7) << 4));
    }

    const int l = tid & 31, wid = tid >> 5;
    const int wm = (wid & 3) * 32, wn = (wid >> 2) * 32;
    const int mat  = l >> 3;
    const int arow = (l & 7) + ((mat & 1) << 3);
    const int acm  = mat >> 1;
    const int brow = (l & 7) + ((mat >> 1) << 3);
    const int bcm  = mat & 1;
    const uint32_t xm = (uint32_t)(l & 7) << 4;
    uint32_t aob[2] = { (uint32_t)(wm + arow) * 128, (uint32_t)(wm + 16 + arow) * 128 };
    uint32_t bob[2] = { (uint32_t)(wn + brow) * 128, (uint32_t)(wn + 16 + brow) * 128 };

    float accg[2][4][4] = {}, accu[2][4][4] = {};
    const int NIT = HDIM / 64;

    #pragma unroll
    for (int s = 0; s < 2; ++s) {
        const uint32_t stg = stgb[s];
        const int k = s * 64;
        #pragma unroll
        for (int j = 0; j < 4; ++j) CPA16(stg + AH + a_dst[j], g_xh + a_off[j] + k);
        #pragma unroll
        for (int j = 0; j < 2; ++j) {
            CPA16(stg + BG + b_dst[j], g_gw16 + b_off[j] + k);
            CPA16(stg + BU + b_dst[j], g_uw16 + b_off[j] + k);
        }
        CPA_COMMIT();
    }

    int cons = 0, prod = 2;
    for (int it = 0; it < NIT; ++it) {
        CPA_WAIT1();
        __syncthreads();
        const uint32_t stg = stgb[cons];
        if (++cons == 3) cons = 0;
        if (it + 2 < NIT) {
            const uint32_t nst = stgb[prod];
            if (++prod == 3) prod = 0;
            const int k = (it + 2) * 64;
            #pragma unroll
            for (int j = 0; j < 4; ++j) CPA16(nst + AH + a_dst[j], g_xh + a_off[j] + k);
            #pragma unroll
            for (int j = 0; j < 2; ++j) {
                CPA16(nst + BG + b_dst[j], g_gw16 + b_off[j] + k);
                CPA16(nst + BU + b_dst[j], g_uw16 + b_off[j] + k);
            }
        }
        CPA_COMMIT();
        #pragma unroll
        for (int kk = 0; kk < 4; ++kk) {
            const uint32_t akb = (((uint32_t)(kk * 2 + acm)) << 4) ^ xm;
            const uint32_t bkb = (((uint32_t)(kk * 2 + bcm)) << 4) ^ xm;
            uint32_t ah[2][4], bg[2][4], bu[2][4];
            ldsm4(ah[0], stg + AH + aob[0] + akb);
            ldsm4(ah[1], stg + AH + aob[1] + akb);
            ldsm4(bg[0], stg + BG + bob[0] + bkb);
            ldsm4(bg[1], stg + BG + bob[1] + bkb);
            ldsm4(bu[0], stg + BU + bob[0] + bkb);
            ldsm4(bu[1], stg + BU + bob[1] + bkb);
            #pragma unroll
            for (int mi = 0; mi < 2; ++mi)
                #pragma unroll
                for (int ni = 0; ni < 4; ++ni) {
                    const int p = ni >> 1, hh = (ni & 1) * 2;
                    mma16816(accg[mi][ni], ah[mi], &bg[p][hh]);
                    mma16816(accu[mi][ni], ah[mi], &bu[p][hh]);
                }
        }
    }

    const int r_ = l >> 2, c2 = (l & 3) * 2;
    #pragma unroll
    for (int mi = 0; mi < 2; ++mi)
        #pragma unroll
        for (int dd = 0; dd < 2; ++dd) {
            int grow = row0 + wm + mi * 16 + r_ + dd * 8;
            if (grow < s1) {
                #pragma unroll
                for (int ni = 0; ni < 4; ++ni) {
                    float g0 = accg[mi][ni][dd * 2],     g1 = accg[mi][ni][dd * 2 + 1];
                    float u0 = accu[mi][ni][dd * 2],     u1 = accu[mi][ni][dd * 2 + 1];
                    float h0 = g0 / (1.f + __expf(-g0)) * u0;
                    float h1 = g1 / (1.f + __expf(-g1)) * u1;
                    __half2 hp = __floats2half2_rn(h0, h1);
                    size_t off = (size_t)grow * IDIM + n0 + wn + ni * 8 + c2;
                    *(__half2*)(g_hh + off) = hp;
                }
            }
        }
}

// ----------------------------------------------- down HMMA GEMM ------------
// 256 thr, BM=128, BN=128, BK=64, 3-stage, 2 CTAs/SM
#define DN_STG   32768
#define DN_SMEM  (3 * DN_STG + 1024)
__global__ __launch_bounds__(256, 2) void down_kernel(float* __restrict__ out) {
    extern __shared__ char smem[];
    const int e  = blockIdx.z;
    const int s0 = g_seg[e], s1 = g_seg[e + 1];
    const int row0 = s0 + blockIdx.y * 128;
    if (row0 >= s1) return;
    const int n0  = blockIdx.x * 128;
    const int tid = threadIdx.x;
    const uint32_t sb = smem_u32(smem);
    enum { AH = 0, BB = 16384 };
    const uint32_t stgb[3] = { sb, sb + DN_STG, sb + 2 * DN_STG };
    int*   toks  = (int*)(smem + 3 * DN_STG);
    float* pwt_s = (float*)(smem + 3 * DN_STG + 512);

    for (int m = tid; m < 128; m += 256) {
        int r = row0 + m;
        int rc = (r < s1) ? r : (s1 - 1);
        toks[m]  = g_perm[rc];
        pwt_s[m] = g_pwt[rc];
    }
    __syncthreads();

    uint32_t a_dst[4]; size_t a_off[4];
    #pragma unroll
    for (int j = 0; j < 4; ++j) {
        int q = tid + 256 * j, ar = q >> 3, ac = q & 7;
        int rc = row0 + ar; if (rc >= s1) rc = s1 - 1;
        a_off[j] = (size_t)rc * IDIM + ac * 8;
        a_dst[j] = ar * 128 + (((uint32_t)ac << 4) ^ ((uint32_t)(ar & 7) << 4));
    }
    uint32_t b_dst[4]; size_t b_off[4];
    #pragma unroll
    for (int j = 0; j < 4; ++j) {
        int q = tid + 256 * j, br = q >> 3, bc = q & 7;
        b_off[j] = ((size_t)e * HDIM + n0 + br) * IDIM + bc * 8;
        b_dst[j] = br * 128 + (((uint32_t)bc << 4) ^ ((uint32_t)(br & 7) << 4));
    }

    const int l = tid & 31, wid = tid >> 5;
    const int wm = (wid & 3) * 32, wn = (wid >> 2) * 64;
    const int mat  = l >> 3;
    const int arow = (l & 7) + ((mat & 1) << 3);
    const int acm  = mat >> 1;
    const int brow = (l & 7) + ((mat >> 1) << 3);
    const int bcm  = mat & 1;
    const uint32_t xm = (uint32_t)(l & 7) << 4;
    uint32_t aob[2] = { (uint32_t)(wm + arow) * 128, (uint32_t)(wm + 16 + arow) * 128 };
    uint32_t bob[4];
    #pragma unroll
    for (int p = 0; p < 4; ++p) bob[p] = (uint32_t)(wn + p * 16 + brow) * 128;

    float acc[2][8][4] = {};
    const int NIT = IDIM / 64;

    #pragma unroll
    for (int s = 0; s < 2; ++s) {
        const uint32_t stg = stgb[s];
        const int k = s * 64;
        #pragma unroll
        for (int j = 0; j < 4; ++j) {
            CPA16(stg + AH + a_dst[j], g_hh + a_off[j] + k);
            CPA16(stg + BB + b_dst[j], g_dw16 + b_off[j] + k);
        }
        CPA_COMMIT();
    }

    int cons = 0, prod = 2;
    for (int it = 0; it < NIT; ++it) {
        CPA_WAIT1();
        __syncthreads();
        const uint32_t stg = stgb[cons];
        if (++cons == 3) cons = 0;
        if (it + 2 < NIT) {
            const uint32_t nst = stgb[prod];
            if (++prod == 3) prod = 0;
            const int k = (it + 2) * 64;
            #pragma unroll
            for (int j = 0; j < 4; ++j) {
                CPA16(nst + AH + a_dst[j], g_hh + a_off[j] + k);
                CPA16(nst + BB + b_dst[j], g_dw16 + b_off[j] + k);
            }
        }
        CPA_COMMIT();
        #pragma unroll
        for (int kk = 0; kk < 4; ++kk) {
            const uint32_t akb = (((uint32_t)(kk * 2 + acm)) << 4) ^ xm;
            const uint32_t bkb = (((uint32_t)(kk * 2 + bcm)) << 4) ^ xm;
            uint32_t ah[2][4], bh[4][4];
            ldsm4(ah[0], stg + AH + aob[0] + akb);
            ldsm4(ah[1], stg + AH + aob[1] + akb);
            #pragma unroll
            for (int p = 0; p < 4; ++p) ldsm4(bh[p], stg + BB + bob[p] + bkb);
            #pragma unroll
            for (int mi = 0; mi < 2; ++mi)
                #pragma unroll
                for (int ni = 0; ni < 8; ++ni) {
                    const int p = ni >> 1, hh = (ni & 1) * 2;
                    mma16816(acc[mi][ni], ah[mi], &bh[p][hh]);
                }
        }
    }

    const int r_ = l >> 2, c2 = (l & 3) * 2;
    #pragma unroll
    for (int mi = 0; mi < 2; ++mi)
        #pragma unroll
        for (int dd = 0; dd < 2; ++dd) {
            int lrow = wm + mi * 16 + r_ + dd * 8;
            int grow = row0 + lrow;
            if (grow < s1) {
                int   tok = toks[lrow];
                float w   = pwt_s[lrow];
                float* op = out + (size_t)tok * HDIM;
                #pragma unroll
                for (int ni = 0; ni < 8; ++ni) {
                    int col = n0 + wn + ni * 8 + c2;
                    atomicAdd(op + col,     w * acc[mi][ni][dd * 2]);
                    atomicAdd(op + col + 1, w * acc[mi][ni][dd * 2 + 1]);
                }
            }
        }
}

// ------------------------------------------------------------- launch ------
extern "C" void kernel_launch(void* const* d_in, const int* in_sizes, int n_in,
                              void* d_out, int out_size) {
    const float* x  = (const float*)d_in[0];
    const float* rw = (const float*)d_in[1];
    const float* gw = (const float*)d_in[2];
    const float* uw = (const float*)d_in[3];
    const float* dw = (const float*)d_in[4];
    float* out = (float*)d_out;

    cudaFuncSetAttribute(gateup_kernel, cudaFuncAttributeMaxDynamicSharedMemorySize,
                         GU_SMEM);
    cudaFuncSetAttribute(down_kernel, cudaFuncAttributeMaxDynamicSharedMemorySize,
                         DN_SMEM);

    prologue_kernel<<<RT_B + PX_B + PW_B, 256>>>(x, rw, gw, uw, out);
    compact_kernel<<<NEXP, 256>>>();

    gateup_kernel<<<GU_TILES + DW_CONV, 256, GU_SMEM>>>(dw);

    dim3 g2(HDIM / 128, NTOK / 128, NEXP);
    down_kernel<<<g2, 256, DN_SMEM>>>(out);
}